// round 1
// baseline (speedup 1.0000x reference)
#include <cuda_runtime.h>
#include <math.h>

#define BSZ   4
#define CCH   1024
#define TLEN  2048
#define LKV   512
#define HH    16
#define DD    64
#define HID   1024
#define SCALE 0.35355339059327373f   // (1024/16)^-0.25

// ---- scratch (allocation-free: __device__ globals) ----
__device__ float g_q [BSZ * TLEN * HID];   // 32 MB, already *SCALE
__device__ float g_k [LKV * HID];          // 2 MB, already *SCALE
__device__ float g_v [LKV * HID];          // 2 MB
__device__ float g_ao[BSZ * TLEN * HID];   // 32 MB attention output

// ============================================================
// GEMM 1: kv = aux(512x1024) @ kv_w^T(1024x2048) + kv_b
//   k = kv[:, :1024] * SCALE ; v = kv[:, 1024:]
// 128x128 tile, BK=8, 256 threads, 8x8 per thread (strided micro-tile)
// ============================================================
__global__ __launch_bounds__(256) void gemm_kv(const float* __restrict__ A,
                                               const float* __restrict__ W,
                                               const float* __restrict__ bias) {
    __shared__ float As[8][129];
    __shared__ float Bs[8][129];
    const int m0 = blockIdx.y * 128, n0 = blockIdx.x * 128;
    const int tid = threadIdx.x, tx = tid & 15, ty = tid >> 4;  // tx->n, ty->m
    float acc[8][8] = {};
    for (int k0 = 0; k0 < 1024; k0 += 8) {
        #pragma unroll
        for (int it = 0; it < 4; it++) {
            int e = tid + it * 256;
            int kk = e & 7, r = e >> 3;
            As[kk][r] = A[(size_t)(m0 + r) * 1024 + k0 + kk];
            Bs[kk][r] = W[(size_t)(n0 + r) * 1024 + k0 + kk];
        }
        __syncthreads();
        #pragma unroll
        for (int kk = 0; kk < 8; kk++) {
            float am[8], bn[8];
            #pragma unroll
            for (int i = 0; i < 8; i++) am[i] = As[kk][ty + i * 16];
            #pragma unroll
            for (int j = 0; j < 8; j++) bn[j] = Bs[kk][tx + j * 16];
            #pragma unroll
            for (int i = 0; i < 8; i++)
                #pragma unroll
                for (int j = 0; j < 8; j++) acc[i][j] += am[i] * bn[j];
        }
        __syncthreads();
    }
    #pragma unroll
    for (int i = 0; i < 8; i++) {
        int m = m0 + ty + i * 16;
        #pragma unroll
        for (int j = 0; j < 8; j++) {
            int n = n0 + tx + j * 16;
            float val = acc[i][j] + bias[n];
            if (n < HID) g_k[(size_t)m * HID + n] = val * SCALE;
            else         g_v[(size_t)m * HID + (n - HID)] = val;
        }
    }
}

// ============================================================
// GEMM 2: q[m,n] = SCALE*(sum_c inpt[b,c,t]*q_w[n,c] + q_b[n]); m=b*T+t
// A is inpt read transposed: contiguous along t (=m) for fixed c.
// ============================================================
__global__ __launch_bounds__(256) void gemm_q(const float* __restrict__ inpt,
                                              const float* __restrict__ W,
                                              const float* __restrict__ bias) {
    __shared__ float As[8][129];
    __shared__ float Bs[8][129];
    const int m0 = blockIdx.y * 128, n0 = blockIdx.x * 128;
    const int b = m0 / TLEN, tbase = m0 % TLEN;   // 2048 % 128 == 0: tile never crosses batch
    const float* Ab = inpt + (size_t)b * CCH * TLEN;
    const int tid = threadIdx.x, tx = tid & 15, ty = tid >> 4;  // tx->n, ty->m
    float acc[8][8] = {};
    for (int k0 = 0; k0 < 1024; k0 += 8) {
        #pragma unroll
        for (int it = 0; it < 4; it++) {
            int e = tid + it * 256;
            int kkA = e >> 7, mm = e & 127;                 // coalesced along t
            As[kkA][mm] = Ab[(size_t)(k0 + kkA) * TLEN + tbase + mm];
            int kkB = e & 7, nn = e >> 3;
            Bs[kkB][nn] = W[(size_t)(n0 + nn) * 1024 + k0 + kkB];
        }
        __syncthreads();
        #pragma unroll
        for (int kk = 0; kk < 8; kk++) {
            float am[8], bn[8];
            #pragma unroll
            for (int i = 0; i < 8; i++) am[i] = As[kk][ty + i * 16];
            #pragma unroll
            for (int j = 0; j < 8; j++) bn[j] = Bs[kk][tx + j * 16];
            #pragma unroll
            for (int i = 0; i < 8; i++)
                #pragma unroll
                for (int j = 0; j < 8; j++) acc[i][j] += am[i] * bn[j];
        }
        __syncthreads();
    }
    #pragma unroll
    for (int i = 0; i < 8; i++) {
        int m = m0 + ty + i * 16;
        #pragma unroll
        for (int j = 0; j < 8; j++) {
            int n = n0 + tx + j * 16;
            g_q[(size_t)m * HID + n] = SCALE * (acc[i][j] + bias[n]);
        }
    }
}

// ============================================================
// Attention: per block = (b, h, 32 queries). Exact softmax over L=512
// scores kept in smem. ~91 KB dynamic smem.
// ============================================================
#define SROW 516
#define ATTN_SMEM ((32 * SROW + 32 * 65 + 64 * 65) * 4)

__global__ __launch_bounds__(256) void attn_kernel() {
    extern __shared__ float sm[];
    float* S   = sm;                 // 32 x SROW scores
    float* Qs  = S + 32 * SROW;      // 32 x 65
    float* KVs = Qs + 32 * 65;       // 64 x 65
    const int tid = threadIdx.x;
    const int b = blockIdx.z, h = blockIdx.y, q0 = blockIdx.x * 32;

    const float* Qg = g_q + ((size_t)(b * TLEN + q0)) * HID + h * DD;
    #pragma unroll
    for (int it = 0; it < 8; it++) {
        int e = tid + it * 256;
        int qi = e >> 6, d = e & 63;
        Qs[qi * 65 + d] = Qg[(size_t)qi * HID + d];
    }

    const int qi = tid >> 3, jb = tid & 7;

    // ---- scores: S = Q @ K^T ----
    for (int l0 = 0; l0 < LKV; l0 += 64) {
        __syncthreads();
        #pragma unroll
        for (int it = 0; it < 16; it++) {
            int e = tid + it * 256;
            int l = e >> 6, d = e & 63;
            KVs[l * 65 + d] = g_k[(size_t)(l0 + l) * HID + h * DD + d];
        }
        __syncthreads();
        float acc[8] = {};
        #pragma unroll 4
        for (int d = 0; d < 64; d++) {
            float qv = Qs[qi * 65 + d];
            #pragma unroll
            for (int j = 0; j < 8; j++) acc[j] += qv * KVs[(jb + j * 8) * 65 + d];
        }
        #pragma unroll
        for (int j = 0; j < 8; j++) S[qi * SROW + l0 + jb + j * 8] = acc[j];
    }
    __syncthreads();

    // ---- softmax over the 512 keys, per row ----
    {
        const int wid = tid >> 5, lane = tid & 31;
        for (int r = wid; r < 32; r += 8) {
            float* row = S + r * SROW;
            float mx = -1e30f;
            #pragma unroll
            for (int i = 0; i < 16; i++) mx = fmaxf(mx, row[lane + i * 32]);
            #pragma unroll
            for (int o = 16; o; o >>= 1) mx = fmaxf(mx, __shfl_xor_sync(0xffffffffu, mx, o));
            float sum = 0.f;
            #pragma unroll
            for (int i = 0; i < 16; i++) {
                float ev = __expf(row[lane + i * 32] - mx);
                row[lane + i * 32] = ev;
                sum += ev;
            }
            #pragma unroll
            for (int o = 16; o; o >>= 1) sum += __shfl_xor_sync(0xffffffffu, sum, o);
            float inv = 1.0f / sum;
            #pragma unroll
            for (int i = 0; i < 16; i++) row[lane + i * 32] *= inv;
        }
    }

    // ---- out = P @ V ----
    float out[8] = {};
    for (int l0 = 0; l0 < LKV; l0 += 64) {
        __syncthreads();
        #pragma unroll
        for (int it = 0; it < 16; it++) {
            int e = tid + it * 256;
            int l = e >> 6, d = e & 63;
            KVs[l * 65 + d] = g_v[(size_t)(l0 + l) * HID + h * DD + d];
        }
        __syncthreads();
        #pragma unroll 4
        for (int l = 0; l < 64; l++) {
            float p = S[qi * SROW + l0 + l];
            #pragma unroll
            for (int j = 0; j < 8; j++) out[j] += p * KVs[l * 65 + jb + j * 8];
        }
    }
    float* Og = g_ao + ((size_t)(b * TLEN + q0 + qi)) * HID + h * DD;
    #pragma unroll
    for (int j = 0; j < 8; j++) Og[jb + j * 8] = out[j];
}

// ============================================================
// GEMM 3: out[b,n,t] = sum_j g_ao[m,j]*out_w[n,j] + out_b[n] + inpt[b,n,t]
// tx->m(t) so the transposed store + residual read are coalesced along t.
// ============================================================
__global__ __launch_bounds__(256) void gemm_out(const float* __restrict__ inpt,
                                                const float* __restrict__ W,
                                                const float* __restrict__ bias,
                                                float* __restrict__ out) {
    __shared__ float As[8][129];
    __shared__ float Bs[8][129];
    const int m0 = blockIdx.y * 128, n0 = blockIdx.x * 128;
    const int b = m0 / TLEN, tbase = m0 % TLEN;
    const int tid = threadIdx.x, tx = tid & 15, ty = tid >> 4;  // tx->m, ty->n
    float acc[8][8] = {};
    for (int k0 = 0; k0 < 1024; k0 += 8) {
        #pragma unroll
        for (int it = 0; it < 4; it++) {
            int e = tid + it * 256;
            int kk = e & 7, r = e >> 3;
            As[kk][r] = g_ao[(size_t)(m0 + r) * HID + k0 + kk];
            Bs[kk][r] = W[(size_t)(n0 + r) * 1024 + k0 + kk];
        }
        __syncthreads();
        #pragma unroll
        for (int kk = 0; kk < 8; kk++) {
            float am[8], bn[8];
            #pragma unroll
            for (int i = 0; i < 8; i++) am[i] = As[kk][tx + i * 16];
            #pragma unroll
            for (int j = 0; j < 8; j++) bn[j] = Bs[kk][ty + j * 16];
            #pragma unroll
            for (int i = 0; i < 8; i++)
                #pragma unroll
                for (int j = 0; j < 8; j++) acc[i][j] += am[i] * bn[j];
        }
        __syncthreads();
    }
    #pragma unroll
    for (int j = 0; j < 8; j++) {
        int n = n0 + ty + j * 16;
        float bi = bias[n];
        #pragma unroll
        for (int i = 0; i < 8; i++) {
            int t = tbase + tx + i * 16;
            size_t idx = ((size_t)b * CCH + n) * TLEN + t;
            out[idx] = acc[i][j] + bi + inpt[idx];
        }
    }
}

// ============================================================
extern "C" void kernel_launch(void* const* d_in, const int* in_sizes, int n_in,
                              void* d_out, int out_size) {
    const float* inpt  = (const float*)d_in[0];
    const float* aux   = (const float*)d_in[1];
    const float* q_w   = (const float*)d_in[2];
    const float* q_b   = (const float*)d_in[3];
    const float* kv_w  = (const float*)d_in[4];
    const float* kv_b  = (const float*)d_in[5];
    const float* out_w = (const float*)d_in[6];
    const float* out_b = (const float*)d_in[7];
    float* out = (float*)d_out;

    cudaFuncSetAttribute(attn_kernel, cudaFuncAttributeMaxDynamicSharedMemorySize, ATTN_SMEM);

    gemm_kv<<<dim3(16, 4), 256>>>(aux, kv_w, kv_b);                 // 512x2048x1024
    gemm_q <<<dim3(8, 64), 256>>>(inpt, q_w, q_b);                  // 8192x1024x1024
    attn_kernel<<<dim3(TLEN / 32, HH, BSZ), 256, ATTN_SMEM>>>();    // 4096 blocks
    gemm_out<<<dim3(8, 64), 256>>>(inpt, out_w, out_b, out);        // 8192x1024x1024
}

// round 3
// speedup vs baseline: 1.8189x; 1.8189x over previous
#include <cuda_runtime.h>
#include <cstdint>

#define BSZ   4
#define CCH   1024
#define TLEN  2048
#define LKV   512
#define HH    16
#define DD    64
#define HID   1024
#define SCALE 0.35355339059327373f   // (1024/16)^-0.25

// ---------------- scratch (__device__ globals; allocation-free) ----------------
__device__ float g_xt [BSZ * TLEN * CCH];   // inpt transposed + tf32-rounded
__device__ float g_qw [HID * CCH];          // tf32-rounded weights
__device__ float g_kvw[2 * HID * CCH];
__device__ float g_ow [CCH * HID];
__device__ float g_aux[LKV * CCH];
__device__ float g_q  [BSZ * TLEN * HID];   // q * SCALE (fp32)
__device__ float g_k  [LKV * HID];          // k * SCALE
__device__ float g_v  [LKV * HID];
__device__ float g_ao [BSZ * TLEN * HID];   // attention out (tf32-rounded)

// ---------------- helpers ----------------
__device__ __forceinline__ uint32_t smem_u32(const void* p) {
    uint32_t a;
    asm("{ .reg .u64 t; cvta.to.shared.u64 t, %1; cvt.u32.u64 %0, t; }" : "=r"(a) : "l"(p));
    return a;
}
__device__ __forceinline__ float tf32r(float x) {
    asm("cvt.rna.tf32.f32 %0, %0;" : "+f"(x));
    return x;
}
__device__ __forceinline__ void fma2(unsigned long long& d, unsigned long long a, unsigned long long b) {
    asm("fma.rn.f32x2 %0, %1, %2, %0;" : "+l"(d) : "l"(a), "l"(b));
}
__device__ __forceinline__ unsigned long long pack2(float x) {
    unsigned long long v; unsigned u = __float_as_uint(x);
    asm("mov.b64 %0, {%1, %1};" : "=l"(v) : "r"(u));
    return v;
}
#define CP_ASYNC(dst, src) asm volatile("cp.async.cg.shared.global [%0], [%1], 16;" :: "r"(dst), "l"(src) : "memory")
#define CP_COMMIT()        asm volatile("cp.async.commit_group;" ::: "memory")
#define CP_WAIT(n)         asm volatile("cp.async.wait_group %0;" :: "n"(n) : "memory")

__device__ __forceinline__ void mma8(float* d, const float* a, float b0, float b1) {
    asm volatile("mma.sync.aligned.m16n8k8.row.col.f32.tf32.tf32.f32 "
        "{%0,%1,%2,%3}, {%4,%5,%6,%7}, {%8,%9}, {%0,%1,%2,%3};"
        : "+f"(d[0]), "+f"(d[1]), "+f"(d[2]), "+f"(d[3])
        : "r"(__float_as_uint(a[0])), "r"(__float_as_uint(a[1])),
          "r"(__float_as_uint(a[2])), "r"(__float_as_uint(a[3])),
          "r"(__float_as_uint(b0)), "r"(__float_as_uint(b1)));
}

// ============================================================
// prep kernels
// ============================================================
__global__ __launch_bounds__(256) void round_copy(const float4* __restrict__ src,
                                                  float4* __restrict__ dst, int n4) {
    int i = blockIdx.x * 256 + threadIdx.x;
    if (i < n4) {
        float4 v = src[i];
        v.x = tf32r(v.x); v.y = tf32r(v.y); v.z = tf32r(v.z); v.w = tf32r(v.w);
        dst[i] = v;
    }
}

__global__ __launch_bounds__(256) void transpose_round(const float* __restrict__ in) {
    __shared__ float tile[32][33];
    int b = blockIdx.z, t0 = blockIdx.x * 32, c0 = blockIdx.y * 32;
    int tx = threadIdx.x & 31, ty = threadIdx.x >> 5;
    const float* p = in + ((size_t)b * CCH + c0) * TLEN + t0;
    #pragma unroll
    for (int r = 0; r < 4; r++)
        tile[ty + 8 * r][tx] = p[(size_t)(ty + 8 * r) * TLEN + tx];
    __syncthreads();
    #pragma unroll
    for (int r = 0; r < 4; r++)
        g_xt[((size_t)b * TLEN + t0 + ty + 8 * r) * CCH + c0 + tx] = tf32r(tile[tx][ty + 8 * r]);
}

// ============================================================
// tf32 mma.sync GEMM: D(128x128 tile) = A(MxK=1024) @ W(NxK)^T
// mode 0: C[m][n] = (acc+bias[n])*scale             (q proj)
// mode 1: split to g_k (*SCALE) / g_v               (kv proj)
// mode 2: out[b][n][t] = acc + bias[n] + resid      (out proj + residual)
// smem: double-buffered As/Bs [2][128][36]; epilogue reuses as Ds[128][132]
// ============================================================
#define GSTR 36
#define GEMM_SMEM (2 * 2 * 128 * GSTR * 4)   // 73728

__global__ __launch_bounds__(256) void gemm_mma(const float* __restrict__ A,
                                                const float* __restrict__ W,
                                                const float* __restrict__ bias,
                                                float* __restrict__ C,
                                                const float* __restrict__ resid,
                                                float scale, int mode) {
    extern __shared__ float sm[];
    float* As = sm;                         // [2][128][36]
    float* Bs = sm + 2 * 128 * GSTR;
    const int tid = threadIdx.x, lane = tid & 31, warp = tid >> 5;
    const int g = lane >> 2, tg = lane & 3;
    const int m_w = (warp & 3) * 32, n_w = (warp >> 2) * 64;
    const int m0 = blockIdx.y * 128, n0 = blockIdx.x * 128;

    const int lrow = tid >> 1, lcol = (tid & 1) * 16;
    const float* gA = A + (size_t)(m0 + lrow) * 1024 + lcol;
    const float* gW = W + (size_t)(n0 + lrow) * 1024 + lcol;
    const uint32_t dA = smem_u32(As) + (lrow * GSTR + lcol) * 4;
    const uint32_t dB = smem_u32(Bs) + (lrow * GSTR + lcol) * 4;

    float acc[2][8][4] = {};

    #define LOAD_STAGE(s, k0) do { \
        uint32_t off = (uint32_t)(s) * (128 * GSTR * 4); \
        _Pragma("unroll") \
        for (int i = 0; i < 4; i++) { \
            CP_ASYNC(dA + off + 16 * i, gA + (k0) + 4 * i); \
            CP_ASYNC(dB + off + 16 * i, gW + (k0) + 4 * i); \
        } \
        CP_COMMIT(); \
    } while (0)

    LOAD_STAGE(0, 0);
    LOAD_STAGE(1, 32);

    for (int kt = 0; kt < 32; kt++) {
        const int s = kt & 1;
        if (kt >= 30) CP_WAIT(0); else CP_WAIT(1);
        __syncthreads();
        const float* as = As + s * 128 * GSTR;
        const float* bs = Bs + s * 128 * GSTR;
        #pragma unroll
        for (int ks = 0; ks < 4; ks++) {
            const int k = ks * 8;
            float a[2][4];
            #pragma unroll
            for (int mi = 0; mi < 2; mi++) {
                const int mr = m_w + mi * 16;
                a[mi][0] = as[(mr + g) * GSTR + k + tg];
                a[mi][1] = as[(mr + g + 8) * GSTR + k + tg];
                a[mi][2] = as[(mr + g) * GSTR + k + tg + 4];
                a[mi][3] = as[(mr + g + 8) * GSTR + k + tg + 4];
            }
            #pragma unroll
            for (int nj = 0; nj < 8; nj++) {
                const int nr = n_w + nj * 8 + g;
                float b0 = bs[nr * GSTR + k + tg];
                float b1 = bs[nr * GSTR + k + tg + 4];
                mma8(acc[0][nj], a[0], b0, b1);
                mma8(acc[1][nj], a[1], b0, b1);
            }
        }
        __syncthreads();
        if (kt + 2 < 32) LOAD_STAGE(s, (kt + 2) * 32);
    }

    // ---- epilogue: fragments -> smem Ds[128][132] -> coalesced global ----
    float* Ds = sm;
    __syncthreads();
    #pragma unroll
    for (int mi = 0; mi < 2; mi++)
        #pragma unroll
        for (int nj = 0; nj < 8; nj++) {
            const int rm = m_w + mi * 16 + g;
            const int cn = n_w + nj * 8 + 2 * tg;
            *(float2*)&Ds[rm * 132 + cn]       = make_float2(acc[mi][nj][0], acc[mi][nj][1]);
            *(float2*)&Ds[(rm + 8) * 132 + cn] = make_float2(acc[mi][nj][2], acc[mi][nj][3]);
        }
    __syncthreads();

    if (mode == 2) {
        const int nr = tid >> 1, mc = (tid & 1) * 64;
        const int b = m0 >> 11, tbase = m0 & 2047;
        const float bi = bias[n0 + nr];
        const size_t obase = ((size_t)(b * CCH + n0 + nr)) * TLEN + tbase + mc;
        #pragma unroll 4
        for (int i = 0; i < 64; i += 4) {
            float4 v;
            v.x = Ds[(mc + i + 0) * 132 + nr];
            v.y = Ds[(mc + i + 1) * 132 + nr];
            v.z = Ds[(mc + i + 2) * 132 + nr];
            v.w = Ds[(mc + i + 3) * 132 + nr];
            float4 rr = *(const float4*)(resid + obase + i);
            v.x += bi + rr.x; v.y += bi + rr.y; v.z += bi + rr.z; v.w += bi + rr.w;
            *(float4*)(C + obase + i) = v;
        }
    } else if (mode == 1) {
        const int r = tid >> 1, c = (tid & 1) * 64;
        const int m = m0 + r;
        if (n0 < HID) {
            float* dst = g_k + (size_t)m * HID + n0 + c;
            #pragma unroll 4
            for (int j = 0; j < 64; j += 4) {
                float4 v = *(float4*)&Ds[r * 132 + c + j];
                v.x = (v.x + bias[n0 + c + j + 0]) * SCALE;
                v.y = (v.y + bias[n0 + c + j + 1]) * SCALE;
                v.z = (v.z + bias[n0 + c + j + 2]) * SCALE;
                v.w = (v.w + bias[n0 + c + j + 3]) * SCALE;
                *(float4*)(dst + j) = v;
            }
        } else {
            float* dst = g_v + (size_t)m * HID + (n0 - HID) + c;
            #pragma unroll 4
            for (int j = 0; j < 64; j += 4) {
                float4 v = *(float4*)&Ds[r * 132 + c + j];
                v.x += bias[n0 + c + j + 0];
                v.y += bias[n0 + c + j + 1];
                v.z += bias[n0 + c + j + 2];
                v.w += bias[n0 + c + j + 3];
                *(float4*)(dst + j) = v;
            }
        }
    } else {
        const int r = tid >> 1, c = (tid & 1) * 64;
        float* dst = C + (size_t)(m0 + r) * HID + n0 + c;
        #pragma unroll 4
        for (int j = 0; j < 64; j += 4) {
            float4 v = *(float4*)&Ds[r * 132 + c + j];
            v.x = (v.x + bias[n0 + c + j + 0]) * scale;
            v.y = (v.y + bias[n0 + c + j + 1]) * scale;
            v.z = (v.z + bias[n0 + c + j + 2]) * scale;
            v.w = (v.w + bias[n0 + c + j + 3]) * scale;
            *(float4*)(dst + j) = v;
        }
    }
}

// ============================================================
// Attention (fp32, packed f32x2 FMA): block = (b, h, 64 queries)
// ============================================================
#define SPAD 516
#define ATTN_SMEM ((64 * SPAD + 64 * 66 + 128 * 66) * 4)

__global__ __launch_bounds__(256) void attn_kernel() {
    extern __shared__ float sm[];
    float* S   = sm;                 // 64 x 516
    float* Qs  = S + 64 * SPAD;      // 64 x 66
    float* KVs = Qs + 64 * 66;       // 128 x 66
    const int tid = threadIdx.x;
    const int b = blockIdx.z, h = blockIdx.y, q0 = blockIdx.x * 64;
    const int wid = tid >> 5, lane = tid & 31;

    const float* Qg = g_q + ((size_t)(b * TLEN + q0)) * HID + h * DD;
    #pragma unroll
    for (int it = 0; it < 8; it++) {
        int e = tid + it * 256, r = e >> 5, p = e & 31;
        *(float2*)&Qs[r * 66 + p * 2] = *(const float2*)&Qg[(size_t)r * HID + p * 2];
    }

    // ---- QK^T: 8q x 4l per thread, f32x2 over d-pairs ----
    for (int l0 = 0; l0 < LKV; l0 += 128) {
        __syncthreads();
        #pragma unroll
        for (int it = 0; it < 16; it++) {
            int e = tid + it * 256, r = e >> 5, p = e & 31;
            *(float2*)&KVs[r * 66 + p * 2] = *(const float2*)&g_k[(size_t)(l0 + r) * HID + h * DD + p * 2];
        }
        __syncthreads();
        unsigned long long acc[8][4] = {};
        #pragma unroll 8
        for (int dp = 0; dp < 32; dp++) {
            unsigned long long kv[4];
            #pragma unroll
            for (int j = 0; j < 4; j++)
                kv[j] = *(unsigned long long*)&KVs[(lane + 32 * j) * 66 + 2 * dp];
            #pragma unroll
            for (int i = 0; i < 8; i++) {
                unsigned long long qv = *(unsigned long long*)&Qs[(wid * 8 + i) * 66 + 2 * dp];
                #pragma unroll
                for (int j = 0; j < 4; j++) fma2(acc[i][j], qv, kv[j]);
            }
        }
        #pragma unroll
        for (int i = 0; i < 8; i++)
            #pragma unroll
            for (int j = 0; j < 4; j++) {
                float2 f = *(float2*)&acc[i][j];
                S[(wid * 8 + i) * SPAD + l0 + lane + 32 * j] = f.x + f.y;
            }
    }
    __syncthreads();

    // ---- softmax ----
    for (int r = wid; r < 64; r += 8) {
        float* row = S + r * SPAD;
        float mx = -1e30f;
        #pragma unroll
        for (int i = 0; i < 16; i++) mx = fmaxf(mx, row[lane + i * 32]);
        #pragma unroll
        for (int o = 16; o; o >>= 1) mx = fmaxf(mx, __shfl_xor_sync(0xffffffffu, mx, o));
        float sum = 0.f;
        #pragma unroll
        for (int i = 0; i < 16; i++) {
            float ev = __expf(row[lane + i * 32] - mx);
            row[lane + i * 32] = ev;
            sum += ev;
        }
        #pragma unroll
        for (int o = 16; o; o >>= 1) sum += __shfl_xor_sync(0xffffffffu, sum, o);
        float inv = 1.0f / sum;
        #pragma unroll
        for (int i = 0; i < 16; i++) row[lane + i * 32] *= inv;
    }

    // ---- P @ V: 2q x 8d per thread ----
    const int qq = tid >> 3, dg = tid & 7;
    unsigned long long o2[2][4] = {};
    for (int l0 = 0; l0 < LKV; l0 += 128) {
        __syncthreads();
        #pragma unroll
        for (int it = 0; it < 16; it++) {
            int e = tid + it * 256, r = e >> 5, p = e & 31;
            *(float2*)&KVs[r * 66 + p * 2] = *(const float2*)&g_v[(size_t)(l0 + r) * HID + h * DD + p * 2];
        }
        __syncthreads();
        #pragma unroll 4
        for (int l = 0; l < 128; l++) {
            unsigned long long P0 = pack2(S[(2 * qq + 0) * SPAD + l0 + l]);
            unsigned long long P1 = pack2(S[(2 * qq + 1) * SPAD + l0 + l]);
            #pragma unroll
            for (int j = 0; j < 4; j++) {
                unsigned long long vv = *(unsigned long long*)&KVs[l * 66 + dg * 8 + 2 * j];
                fma2(o2[0][j], P0, vv);
                fma2(o2[1][j], P1, vv);
            }
        }
    }
    float* Og = g_ao + ((size_t)(b * TLEN + q0 + 2 * qq)) * HID + h * DD + dg * 8;
    #pragma unroll
    for (int i = 0; i < 2; i++)
        #pragma unroll
        for (int j = 0; j < 4; j++) {
            float2 f = *(float2*)&o2[i][j];
            f.x = tf32r(f.x); f.y = tf32r(f.y);
            *(float2*)&Og[(size_t)i * HID + 2 * j] = f;
        }
}

// ============================================================
extern "C" void kernel_launch(void* const* d_in, const int* in_sizes, int n_in,
                              void* d_out, int out_size) {
    const float* inpt  = (const float*)d_in[0];
    const float* aux   = (const float*)d_in[1];
    const float* q_w   = (const float*)d_in[2];
    const float* q_b   = (const float*)d_in[3];
    const float* kv_w  = (const float*)d_in[4];
    const float* kv_b  = (const float*)d_in[5];
    const float* out_w = (const float*)d_in[6];
    const float* out_b = (const float*)d_in[7];
    float* out = (float*)d_out;

    void *p_qw, *p_kvw, *p_ow, *p_aux, *p_xt, *p_q, *p_ao;
    cudaGetSymbolAddress(&p_qw, g_qw);
    cudaGetSymbolAddress(&p_kvw, g_kvw);
    cudaGetSymbolAddress(&p_ow, g_ow);
    cudaGetSymbolAddress(&p_aux, g_aux);
    cudaGetSymbolAddress(&p_xt, g_xt);
    cudaGetSymbolAddress(&p_q, g_q);
    cudaGetSymbolAddress(&p_ao, g_ao);

    cudaFuncSetAttribute(gemm_mma, cudaFuncAttributeMaxDynamicSharedMemorySize, GEMM_SMEM);
    cudaFuncSetAttribute(attn_kernel, cudaFuncAttributeMaxDynamicSharedMemorySize, ATTN_SMEM);

    round_copy<<<(HID * CCH / 4 + 255) / 256, 256>>>((const float4*)q_w, (float4*)p_qw, HID * CCH / 4);
    round_copy<<<(2 * HID * CCH / 4 + 255) / 256, 256>>>((const float4*)kv_w, (float4*)p_kvw, 2 * HID * CCH / 4);
    round_copy<<<(CCH * HID / 4 + 255) / 256, 256>>>((const float4*)out_w, (float4*)p_ow, CCH * HID / 4);
    round_copy<<<(LKV * CCH / 4 + 255) / 256, 256>>>((const float4*)aux, (float4*)p_aux, LKV * CCH / 4);
    transpose_round<<<dim3(TLEN / 32, CCH / 32, BSZ), 256>>>(inpt);

    gemm_mma<<<dim3(16, 4), 256, GEMM_SMEM>>>((const float*)p_aux, (const float*)p_kvw,
                                              kv_b, nullptr, nullptr, 1.0f, 1);
    gemm_mma<<<dim3(8, 64), 256, GEMM_SMEM>>>((const float*)p_xt, (const float*)p_qw,
                                              q_b, (float*)p_q, nullptr, SCALE, 0);

    attn_kernel<<<dim3(TLEN / 64, HH, BSZ), 256, ATTN_SMEM>>>();

    gemm_mma<<<dim3(8, 64), 256, GEMM_SMEM>>>((const float*)p_ao, (const float*)p_ow,
                                              out_b, out, inpt, 1.0f, 2);
}

// round 4
// speedup vs baseline: 3.2420x; 1.7824x over previous
#include <cuda_runtime.h>
#include <cstdint>

#define BSZ   4
#define CCH   1024
#define TLEN  2048
#define LKV   512
#define HH    16
#define DD    64
#define HID   1024
#define SCALE 0.35355339059327373f   // (1024/16)^-0.25

// ---------------- scratch (__device__ globals; allocation-free) ----------------
__device__ float g_xt [BSZ * TLEN * CCH];   // inpt transposed + tf32-rounded
__device__ float g_qw [HID * CCH];          // tf32-rounded weights
__device__ float g_kvw[2 * HID * CCH];
__device__ float g_ow [CCH * HID];
__device__ float g_aux[LKV * CCH];
__device__ float g_qh [BSZ * HH * TLEN * DD]; // q head-major [b][h][t][d], *SCALE, tf32
__device__ float g_kh [HH * LKV * DD];        // k head-major [h][l][d], *SCALE, tf32
__device__ float g_v  [LKV * HID];            // v plain [l][h*64+d]
__device__ float g_vt [HID * LKV];            // v transposed [h*64+d][l], tf32
__device__ float g_ao [BSZ * TLEN * HID];     // attention out [m][j], tf32

// ---------------- helpers ----------------
__device__ __forceinline__ uint32_t smem_u32(const void* p) {
    uint32_t a;
    asm("{ .reg .u64 t; cvta.to.shared.u64 t, %1; cvt.u32.u64 %0, t; }" : "=r"(a) : "l"(p));
    return a;
}
__device__ __forceinline__ float tf32r(float x) {
    asm("cvt.rna.tf32.f32 %0, %0;" : "+f"(x));
    return x;
}
#define CP_ASYNC(dst, src) asm volatile("cp.async.cg.shared.global [%0], [%1], 16;" :: "r"(dst), "l"(src) : "memory")
#define CP_COMMIT()        asm volatile("cp.async.commit_group;" ::: "memory")
#define CP_WAIT(n)         asm volatile("cp.async.wait_group %0;" :: "n"(n) : "memory")

__device__ __forceinline__ void mma8(float* d, const float* a, float b0, float b1) {
    asm volatile("mma.sync.aligned.m16n8k8.row.col.f32.tf32.tf32.f32 "
        "{%0,%1,%2,%3}, {%4,%5,%6,%7}, {%8,%9}, {%0,%1,%2,%3};"
        : "+f"(d[0]), "+f"(d[1]), "+f"(d[2]), "+f"(d[3])
        : "r"(__float_as_uint(a[0])), "r"(__float_as_uint(a[1])),
          "r"(__float_as_uint(a[2])), "r"(__float_as_uint(a[3])),
          "r"(__float_as_uint(b0)), "r"(__float_as_uint(b1)));
}

// ============================================================
// prep kernels
// ============================================================
__global__ __launch_bounds__(256) void round_copy(const float4* __restrict__ src,
                                                  float4* __restrict__ dst, int n4) {
    int i = blockIdx.x * 256 + threadIdx.x;
    if (i < n4) {
        float4 v = src[i];
        v.x = tf32r(v.x); v.y = tf32r(v.y); v.z = tf32r(v.z); v.w = tf32r(v.w);
        dst[i] = v;
    }
}

__global__ __launch_bounds__(256) void transpose_round(const float* __restrict__ in) {
    __shared__ float tile[32][33];
    int b = blockIdx.z, t0 = blockIdx.x * 32, c0 = blockIdx.y * 32;
    int tx = threadIdx.x & 31, ty = threadIdx.x >> 5;
    const float* p = in + ((size_t)b * CCH + c0) * TLEN + t0;
    #pragma unroll
    for (int r = 0; r < 4; r++)
        tile[ty + 8 * r][tx] = p[(size_t)(ty + 8 * r) * TLEN + tx];
    __syncthreads();
    #pragma unroll
    for (int r = 0; r < 4; r++)
        g_xt[((size_t)b * TLEN + t0 + ty + 8 * r) * CCH + c0 + tx] = tf32r(tile[tx][ty + 8 * r]);
}

// v [512][1024] -> vt [1024][512], tf32-rounded
__global__ __launch_bounds__(256) void v_transpose() {
    __shared__ float tile[32][33];
    int l0 = blockIdx.x * 32, c0 = blockIdx.y * 32;
    int tx = threadIdx.x & 31, ty = threadIdx.x >> 5;
    #pragma unroll
    for (int r = 0; r < 4; r++)
        tile[ty + 8 * r][tx] = g_v[(size_t)(l0 + ty + 8 * r) * HID + c0 + tx];
    __syncthreads();
    #pragma unroll
    for (int r = 0; r < 4; r++)
        g_vt[(size_t)(c0 + ty + 8 * r) * LKV + l0 + tx] = tf32r(tile[tx][ty + 8 * r]);
}

// ============================================================
// tf32 mma.sync GEMM: 128x128 tile, K=1024
// mode 0: g_qh[b][h][t][d] = tf32r((acc+bias)*SCALE)
// mode 1: n<1024 -> g_kh[h][l][d] = tf32r((acc+bias)*SCALE) ; else g_v plain
// mode 2: out[b][n][t] = acc + bias[n] + resid
// ============================================================
#define GSTR 36
#define GEMM_SMEM (2 * 2 * 128 * GSTR * 4)   // 73728

__global__ __launch_bounds__(256) void gemm_mma(const float* __restrict__ A,
                                                const float* __restrict__ W,
                                                const float* __restrict__ bias,
                                                float* __restrict__ C,
                                                const float* __restrict__ resid,
                                                int mode) {
    extern __shared__ float sm[];
    float* As = sm;
    float* Bs = sm + 2 * 128 * GSTR;
    const int tid = threadIdx.x, lane = tid & 31, warp = tid >> 5;
    const int g = lane >> 2, tg = lane & 3;
    const int m_w = (warp & 3) * 32, n_w = (warp >> 2) * 64;
    const int m0 = blockIdx.y * 128, n0 = blockIdx.x * 128;

    const int lrow = tid >> 1, lcol = (tid & 1) * 16;
    const float* gA = A + (size_t)(m0 + lrow) * 1024 + lcol;
    const float* gW = W + (size_t)(n0 + lrow) * 1024 + lcol;
    const uint32_t dA = smem_u32(As) + (lrow * GSTR + lcol) * 4;
    const uint32_t dB = smem_u32(Bs) + (lrow * GSTR + lcol) * 4;

    float acc[2][8][4] = {};

    #define LOAD_STAGE(s, k0) do { \
        uint32_t off = (uint32_t)(s) * (128 * GSTR * 4); \
        _Pragma("unroll") \
        for (int i = 0; i < 4; i++) { \
            CP_ASYNC(dA + off + 16 * i, gA + (k0) + 4 * i); \
            CP_ASYNC(dB + off + 16 * i, gW + (k0) + 4 * i); \
        } \
        CP_COMMIT(); \
    } while (0)

    LOAD_STAGE(0, 0);
    LOAD_STAGE(1, 32);

    for (int kt = 0; kt < 32; kt++) {
        const int s = kt & 1;
        if (kt >= 30) CP_WAIT(0); else CP_WAIT(1);
        __syncthreads();
        const float* as = As + s * 128 * GSTR;
        const float* bs = Bs + s * 128 * GSTR;
        #pragma unroll
        for (int ks = 0; ks < 4; ks++) {
            const int k = ks * 8;
            float a[2][4];
            #pragma unroll
            for (int mi = 0; mi < 2; mi++) {
                const int mr = m_w + mi * 16;
                a[mi][0] = as[(mr + g) * GSTR + k + tg];
                a[mi][1] = as[(mr + g + 8) * GSTR + k + tg];
                a[mi][2] = as[(mr + g) * GSTR + k + tg + 4];
                a[mi][3] = as[(mr + g + 8) * GSTR + k + tg + 4];
            }
            #pragma unroll
            for (int nj = 0; nj < 8; nj++) {
                const int nr = n_w + nj * 8 + g;
                float b0 = bs[nr * GSTR + k + tg];
                float b1 = bs[nr * GSTR + k + tg + 4];
                mma8(acc[0][nj], a[0], b0, b1);
                mma8(acc[1][nj], a[1], b0, b1);
            }
        }
        __syncthreads();
        if (kt + 2 < 32) LOAD_STAGE(s, (kt + 2) * 32);
    }

    float* Ds = sm;
    __syncthreads();
    #pragma unroll
    for (int mi = 0; mi < 2; mi++)
        #pragma unroll
        for (int nj = 0; nj < 8; nj++) {
            const int rm = m_w + mi * 16 + g;
            const int cn = n_w + nj * 8 + 2 * tg;
            *(float2*)&Ds[rm * 132 + cn]       = make_float2(acc[mi][nj][0], acc[mi][nj][1]);
            *(float2*)&Ds[(rm + 8) * 132 + cn] = make_float2(acc[mi][nj][2], acc[mi][nj][3]);
        }
    __syncthreads();

    if (mode == 2) {
        const int nr = tid >> 1, mc = (tid & 1) * 64;
        const int b = m0 >> 11, tbase = m0 & 2047;
        const float bi = bias[n0 + nr];
        const size_t obase = ((size_t)(b * CCH + n0 + nr)) * TLEN + tbase + mc;
        #pragma unroll 4
        for (int i = 0; i < 64; i += 4) {
            float4 v;
            v.x = Ds[(mc + i + 0) * 132 + nr];
            v.y = Ds[(mc + i + 1) * 132 + nr];
            v.z = Ds[(mc + i + 2) * 132 + nr];
            v.w = Ds[(mc + i + 3) * 132 + nr];
            float4 rr = *(const float4*)(resid + obase + i);
            v.x += bi + rr.x; v.y += bi + rr.y; v.z += bi + rr.z; v.w += bi + rr.w;
            *(float4*)(C + obase + i) = v;
        }
    } else if (mode == 1) {
        const int r = tid >> 1, c = (tid & 1) * 64;
        const int m = m0 + r;   // l
        if (n0 < HID) {
            const int h = (n0 + c) >> 6;
            float* dst = g_kh + ((size_t)h * LKV + m) * DD;
            #pragma unroll 4
            for (int j = 0; j < 64; j += 4) {
                float4 v = *(float4*)&Ds[r * 132 + c + j];
                v.x = tf32r((v.x + bias[n0 + c + j + 0]) * SCALE);
                v.y = tf32r((v.y + bias[n0 + c + j + 1]) * SCALE);
                v.z = tf32r((v.z + bias[n0 + c + j + 2]) * SCALE);
                v.w = tf32r((v.w + bias[n0 + c + j + 3]) * SCALE);
                *(float4*)(dst + j) = v;
            }
        } else {
            float* dst = g_v + (size_t)m * HID + (n0 - HID) + c;
            #pragma unroll 4
            for (int j = 0; j < 64; j += 4) {
                float4 v = *(float4*)&Ds[r * 132 + c + j];
                v.x += bias[n0 + c + j + 0];
                v.y += bias[n0 + c + j + 1];
                v.z += bias[n0 + c + j + 2];
                v.w += bias[n0 + c + j + 3];
                *(float4*)(dst + j) = v;
            }
        }
    } else {
        const int r = tid >> 1, c = (tid & 1) * 64;
        const int b = m0 >> 11, t = (m0 & 2047) + r;
        const int h = (n0 + c) >> 6;
        float* dst = g_qh + (((size_t)(b * HH + h)) * TLEN + t) * DD;
        #pragma unroll 4
        for (int j = 0; j < 64; j += 4) {
            float4 v = *(float4*)&Ds[r * 132 + c + j];
            v.x = tf32r((v.x + bias[n0 + c + j + 0]) * SCALE);
            v.y = tf32r((v.y + bias[n0 + c + j + 1]) * SCALE);
            v.z = tf32r((v.z + bias[n0 + c + j + 2]) * SCALE);
            v.w = tf32r((v.w + bias[n0 + c + j + 3]) * SCALE);
            *(float4*)(dst + j) = v;
        }
    }
}

// ============================================================
// Tensor-core attention: block = (b, h, 64 queries), 256 thr.
// S[64][512] in smem; QK^T and P@V via mma.sync tf32.
// K/V chunks (128 keys) double-buffered via cp.async.
// ============================================================
#define SPAD 520
#define QSTR 68
#define KSTR 68
#define VSTR 136
#define CHUNK_F 8704
#define ATTN_SMEM ((64 * SPAD + 64 * QSTR + 2 * CHUNK_F) * 4)   // 220160

__global__ __launch_bounds__(256) void attn_tc() {
    extern __shared__ float sm[];
    float* S  = sm;                    // 64 x 520
    float* Qs = S + 64 * SPAD;         // 64 x 68
    float* KV = Qs + 64 * QSTR;        // 2 x 8704
    const uint32_t kvb = smem_u32(KV);
    const int tid = threadIdx.x, wid = tid >> 5, lane = tid & 31;
    const int g = lane >> 2, tg = lane & 3;
    const int b = blockIdx.z, h = blockIdx.y, q0 = blockIdx.x * 64;
    const int wm = (wid & 3) * 16;
    const int wnK = (wid >> 2) * 64;   // n offset within 128-key chunk
    const int wnV = (wid >> 2) * 32;   // d offset within 64

    // load Q tile (contiguous head-major)
    const float* Qg = g_qh + (((size_t)(b * HH + h)) * TLEN + q0) * DD;
    #pragma unroll
    for (int j = 0; j < 4; j++) {
        int idx = tid + j * 256, row = idx >> 4, c4 = idx & 15;
        *(float4*)&Qs[row * QSTR + c4 * 4] = *(const float4*)&Qg[row * 64 + c4 * 4];
    }

    #define PF(i) do { \
        int _buf = (i) & 1; \
        uint32_t _d0 = kvb + (uint32_t)_buf * (CHUNK_F * 4); \
        if ((i) < 4) { \
            const float* _src = g_kh + ((size_t)h * LKV + (i) * 128) * DD; \
            _Pragma("unroll") \
            for (int _j = 0; _j < 8; _j++) { \
                int _e = tid + _j * 256, _r = _e >> 4, _c = _e & 15; \
                CP_ASYNC(_d0 + (uint32_t)(_r * KSTR + _c * 4) * 4, _src + _r * 64 + _c * 4); \
            } \
        } else { \
            const float* _src = g_vt + (size_t)h * 64 * LKV + ((i) - 4) * 128; \
            _Pragma("unroll") \
            for (int _j = 0; _j < 8; _j++) { \
                int _e = tid + _j * 256, _r = _e >> 5, _c = _e & 31; \
                CP_ASYNC(_d0 + (uint32_t)(_r * VSTR + _c * 4) * 4, _src + (size_t)_r * LKV + _c * 4); \
            } \
        } \
        CP_COMMIT(); \
    } while (0)

    PF(0); PF(1);
    float oacc[4][4] = {};

    for (int i = 0; i < 8; i++) {
        if (i == 7) CP_WAIT(0); else CP_WAIT(1);
        __syncthreads();
        const float* kv = KV + (i & 1) * CHUNK_F;
        if (i < 4) {
            const int l0 = i * 128;
            float acc[8][4] = {};
            #pragma unroll
            for (int ks = 0; ks < 8; ks++) {
                const int k = ks * 8;
                float a[4];
                a[0] = Qs[(wm + g) * QSTR + k + tg];
                a[1] = Qs[(wm + g + 8) * QSTR + k + tg];
                a[2] = Qs[(wm + g) * QSTR + k + tg + 4];
                a[3] = Qs[(wm + g + 8) * QSTR + k + tg + 4];
                #pragma unroll
                for (int nj = 0; nj < 8; nj++) {
                    const int nr = wnK + nj * 8 + g;
                    mma8(acc[nj], a, kv[nr * KSTR + k + tg], kv[nr * KSTR + k + tg + 4]);
                }
            }
            #pragma unroll
            for (int nj = 0; nj < 8; nj++) {
                const int col = l0 + wnK + nj * 8 + 2 * tg;
                *(float2*)&S[(wm + g) * SPAD + col]     = make_float2(acc[nj][0], acc[nj][1]);
                *(float2*)&S[(wm + g + 8) * SPAD + col] = make_float2(acc[nj][2], acc[nj][3]);
            }
        } else {
            const int l0 = (i - 4) * 128;
            #pragma unroll
            for (int ks = 0; ks < 16; ks++) {
                const int k = ks * 8;
                float a[4];
                a[0] = S[(wm + g) * SPAD + l0 + k + tg];
                a[1] = S[(wm + g + 8) * SPAD + l0 + k + tg];
                a[2] = S[(wm + g) * SPAD + l0 + k + tg + 4];
                a[3] = S[(wm + g + 8) * SPAD + l0 + k + tg + 4];
                #pragma unroll
                for (int nj = 0; nj < 4; nj++) {
                    const int nr = wnV + nj * 8 + g;
                    mma8(oacc[nj], a, kv[nr * VSTR + k + tg], kv[nr * VSTR + k + tg + 4]);
                }
            }
        }
        __syncthreads();
        if (i == 3) {
            // softmax over 512 keys; P tf32-rounded in place
            for (int r = wid; r < 64; r += 8) {
                float* row = S + r * SPAD;
                float mx = -1e30f;
                #pragma unroll
                for (int u = 0; u < 16; u++) mx = fmaxf(mx, row[lane + u * 32]);
                #pragma unroll
                for (int o = 16; o; o >>= 1) mx = fmaxf(mx, __shfl_xor_sync(0xffffffffu, mx, o));
                float sum = 0.f;
                #pragma unroll
                for (int u = 0; u < 16; u++) {
                    float ev = __expf(row[lane + u * 32] - mx);
                    row[lane + u * 32] = ev;
                    sum += ev;
                }
                #pragma unroll
                for (int o = 16; o; o >>= 1) sum += __shfl_xor_sync(0xffffffffu, sum, o);
                float inv = 1.0f / sum;
                #pragma unroll
                for (int u = 0; u < 16; u++) row[lane + u * 32] = tf32r(row[lane + u * 32] * inv);
            }
            __syncthreads();
        }
        if (i + 2 < 8) PF(i + 2);
    }

    // epilogue: O fragments -> g_ao [m][h*64+d], tf32-rounded
    #pragma unroll
    for (int nj = 0; nj < 4; nj++) {
        const int d = h * 64 + wnV + nj * 8 + 2 * tg;
        const int q = q0 + wm + g;
        float2 v0 = make_float2(tf32r(oacc[nj][0]), tf32r(oacc[nj][1]));
        float2 v1 = make_float2(tf32r(oacc[nj][2]), tf32r(oacc[nj][3]));
        *(float2*)&g_ao[((size_t)b * TLEN + q) * HID + d]     = v0;
        *(float2*)&g_ao[((size_t)b * TLEN + q + 8) * HID + d] = v1;
    }
}

// ============================================================
extern "C" void kernel_launch(void* const* d_in, const int* in_sizes, int n_in,
                              void* d_out, int out_size) {
    const float* inpt  = (const float*)d_in[0];
    const float* aux   = (const float*)d_in[1];
    const float* q_w   = (const float*)d_in[2];
    const float* q_b   = (const float*)d_in[3];
    const float* kv_w  = (const float*)d_in[4];
    const float* kv_b  = (const float*)d_in[5];
    const float* out_w = (const float*)d_in[6];
    const float* out_b = (const float*)d_in[7];
    float* out = (float*)d_out;

    void *p_qw, *p_kvw, *p_ow, *p_aux, *p_xt, *p_ao;
    cudaGetSymbolAddress(&p_qw, g_qw);
    cudaGetSymbolAddress(&p_kvw, g_kvw);
    cudaGetSymbolAddress(&p_ow, g_ow);
    cudaGetSymbolAddress(&p_aux, g_aux);
    cudaGetSymbolAddress(&p_xt, g_xt);
    cudaGetSymbolAddress(&p_ao, g_ao);

    cudaFuncSetAttribute(gemm_mma, cudaFuncAttributeMaxDynamicSharedMemorySize, GEMM_SMEM);
    cudaFuncSetAttribute(attn_tc, cudaFuncAttributeMaxDynamicSharedMemorySize, ATTN_SMEM);

    round_copy<<<(HID * CCH / 4 + 255) / 256, 256>>>((const float4*)q_w, (float4*)p_qw, HID * CCH / 4);
    round_copy<<<(2 * HID * CCH / 4 + 255) / 256, 256>>>((const float4*)kv_w, (float4*)p_kvw, 2 * HID * CCH / 4);
    round_copy<<<(CCH * HID / 4 + 255) / 256, 256>>>((const float4*)out_w, (float4*)p_ow, CCH * HID / 4);
    round_copy<<<(LKV * CCH / 4 + 255) / 256, 256>>>((const float4*)aux, (float4*)p_aux, LKV * CCH / 4);
    transpose_round<<<dim3(TLEN / 32, CCH / 32, BSZ), 256>>>(inpt);

    gemm_mma<<<dim3(16, 4), 256, GEMM_SMEM>>>((const float*)p_aux, (const float*)p_kvw,
                                              kv_b, nullptr, nullptr, 1);
    v_transpose<<<dim3(LKV / 32, HID / 32), 256>>>();

    gemm_mma<<<dim3(8, 64), 256, GEMM_SMEM>>>((const float*)p_xt, (const float*)p_qw,
                                              q_b, nullptr, nullptr, 0);

    attn_tc<<<dim3(TLEN / 64, HH, BSZ), 256, ATTN_SMEM>>>();

    gemm_mma<<<dim3(8, 64), 256, GEMM_SMEM>>>((const float*)p_ao, (const float*)p_ow,
                                              out_b, out, inpt, 2);
}

// round 6
// speedup vs baseline: 7.3399x; 2.2640x over previous
#include <cuda_runtime.h>
#include <cuda_fp16.h>
#include <cstdint>

#define BSZ   4
#define CCH   1024
#define TLEN  2048
#define LKV   512
#define HH    16
#define DD    64
#define HID   1024
#define SCALE 0.35355339059327373f   // (1024/16)^-0.25

// ---------------- scratch (__device__ globals; allocation-free) ----------------
__device__ __half g_xt [BSZ * TLEN * CCH];   // inpt transposed, fp16
__device__ __half g_qw [HID * CCH];
__device__ __half g_kvw[2 * HID * CCH];
__device__ __half g_ow [CCH * HID];
__device__ __half g_aux[LKV * CCH];
__device__ __half g_qh [BSZ * HH * TLEN * DD]; // q head-major [b][h][t][d], *SCALE
__device__ __half g_kh [HH * LKV * DD];        // k head-major [h][l][d], *SCALE
__device__ __half g_vt [HID * LKV];            // v transposed [h*64+d][l]
__device__ __half g_ao [BSZ * TLEN * HID];     // attention out [m][j]

// ---------------- helpers ----------------
__device__ __forceinline__ uint32_t smem_u32(const void* p) {
    uint32_t a;
    asm("{ .reg .u64 t; cvta.to.shared.u64 t, %1; cvt.u32.u64 %0, t; }" : "=r"(a) : "l"(p));
    return a;
}
__device__ __forceinline__ uint32_t U32(const __half* p) { return *(const uint32_t*)p; }
__device__ __forceinline__ uint32_t packh2(float x, float y) {
    __half2 h = __floats2half2_rn(x, y);
    return *(uint32_t*)&h;
}

#define CP_ASYNC(dst, src) asm volatile("cp.async.cg.shared.global [%0], [%1], 16;" :: "r"(dst), "l"(src) : "memory")
#define CP_COMMIT()        asm volatile("cp.async.commit_group;" ::: "memory")
#define CP_WAIT(n)         asm volatile("cp.async.wait_group %0;" :: "n"(n) : "memory")

__device__ __forceinline__ void mma16(float* d, const uint32_t* a, uint32_t b0, uint32_t b1) {
    asm volatile("mma.sync.aligned.m16n8k16.row.col.f32.f16.f16.f32 "
        "{%0,%1,%2,%3}, {%4,%5,%6,%7}, {%8,%9}, {%0,%1,%2,%3};"
        : "+f"(d[0]), "+f"(d[1]), "+f"(d[2]), "+f"(d[3])
        : "r"(a[0]), "r"(a[1]), "r"(a[2]), "r"(a[3]), "r"(b0), "r"(b1));
}

// ============================================================
// prep: fp32 -> fp16 (rn)
// ============================================================
__global__ __launch_bounds__(256) void round_half(const float4* __restrict__ src,
                                                  __half* __restrict__ dst, int n4) {
    int i = blockIdx.x * 256 + threadIdx.x;
    if (i < n4) {
        float4 v = src[i];
        __half2* d2 = (__half2*)(dst + 4 * (size_t)i);
        d2[0] = __floats2half2_rn(v.x, v.y);
        d2[1] = __floats2half2_rn(v.z, v.w);
    }
}

__global__ __launch_bounds__(256) void transpose_half(const float* __restrict__ in) {
    __shared__ float tile[32][33];
    int b = blockIdx.z, t0 = blockIdx.x * 32, c0 = blockIdx.y * 32;
    int tx = threadIdx.x & 31, ty = threadIdx.x >> 5;
    const float* p = in + ((size_t)b * CCH + c0) * TLEN + t0;
    #pragma unroll
    for (int r = 0; r < 4; r++)
        tile[ty + 8 * r][tx] = p[(size_t)(ty + 8 * r) * TLEN + tx];
    __syncthreads();
    #pragma unroll
    for (int r = 0; r < 4; r++)
        g_xt[((size_t)b * TLEN + t0 + ty + 8 * r) * CCH + c0 + tx] =
            __float2half_rn(tile[tx][ty + 8 * r]);
}

// ============================================================
// fp16 mma GEMM: 128x128 tile, K=1024, BK=32, double-buffered cp.async
// mode 0: g_qh[b][h][t][d] = h((acc+bias)*SCALE)     (q proj)
// mode 1: n<1024 -> g_kh ; else g_vt (transposed)    (kv proj)
// mode 2: out[b][n][t] = acc + bias[n] + resid       (out proj + residual)
// ============================================================
#define AH 40                         // smem stride in halfs
#define STAGE_B (128 * AH * 2)        // 10240 bytes per matrix stage
#define GEMM_SMEM (128 * 132 * 4)     // epilogue Ds dominates (67584)

__global__ __launch_bounds__(256) void gemm_mma(const __half* __restrict__ A,
                                                const __half* __restrict__ W,
                                                const float* __restrict__ bias,
                                                float* __restrict__ C,
                                                const float* __restrict__ resid,
                                                int mode) {
    extern __shared__ float sm[];
    __half* As = (__half*)sm;                    // [2][128][40]
    __half* Bs = As + 2 * 128 * AH;
    const int tid = threadIdx.x, lane = tid & 31, warp = tid >> 5;
    const int g = lane >> 2, tg = lane & 3;
    const int m_w = (warp & 3) * 32, n_w = (warp >> 2) * 64;
    const int m0 = blockIdx.y * 128, n0 = blockIdx.x * 128;

    const int r0 = tid >> 2, ch = (tid & 3) * 8;
    const __half* gA = A + (size_t)(m0 + r0) * 1024 + ch;
    const __half* gW = W + (size_t)(n0 + r0) * 1024 + ch;
    const uint32_t dA = smem_u32(As) + (r0 * AH + ch) * 2;
    const uint32_t dB = smem_u32(Bs) + (r0 * AH + ch) * 2;

    float acc[2][8][4] = {};

    #define LOAD_STAGE(s, k0) do { \
        uint32_t off = (uint32_t)(s) * STAGE_B; \
        CP_ASYNC(dA + off, gA + (k0)); \
        CP_ASYNC(dA + off + 64 * AH * 2, gA + (k0) + (size_t)64 * 1024); \
        CP_ASYNC(dB + off, gW + (k0)); \
        CP_ASYNC(dB + off + 64 * AH * 2, gW + (k0) + (size_t)64 * 1024); \
        CP_COMMIT(); \
    } while (0)

    LOAD_STAGE(0, 0);
    LOAD_STAGE(1, 32);

    for (int kt = 0; kt < 32; kt++) {
        const int s = kt & 1;
        if (kt >= 30) CP_WAIT(0); else CP_WAIT(1);
        __syncthreads();
        const __half* as = As + s * 128 * AH;
        const __half* bs = Bs + s * 128 * AH;
        #pragma unroll
        for (int ks = 0; ks < 2; ks++) {
            const int k = ks * 16;
            uint32_t a[2][4];
            #pragma unroll
            for (int mi = 0; mi < 2; mi++) {
                const int mr = m_w + mi * 16;
                a[mi][0] = U32(as + (mr + g) * AH + k + 2 * tg);
                a[mi][1] = U32(as + (mr + g + 8) * AH + k + 2 * tg);
                a[mi][2] = U32(as + (mr + g) * AH + k + 8 + 2 * tg);
                a[mi][3] = U32(as + (mr + g + 8) * AH + k + 8 + 2 * tg);
            }
            #pragma unroll
            for (int nj = 0; nj < 8; nj++) {
                const int nr = n_w + nj * 8 + g;
                uint32_t b0 = U32(bs + nr * AH + k + 2 * tg);
                uint32_t b1 = U32(bs + nr * AH + k + 8 + 2 * tg);
                mma16(acc[0][nj], a[0], b0, b1);
                mma16(acc[1][nj], a[1], b0, b1);
            }
        }
        __syncthreads();
        if (kt + 2 < 32) LOAD_STAGE(s, (kt + 2) * 32);
    }

    // ---- epilogue via smem Ds[128][132] (fp32) ----
    float* Ds = sm;
    __syncthreads();
    #pragma unroll
    for (int mi = 0; mi < 2; mi++)
        #pragma unroll
        for (int nj = 0; nj < 8; nj++) {
            const int rm = m_w + mi * 16 + g;
            const int cn = n_w + nj * 8 + 2 * tg;
            *(float2*)&Ds[rm * 132 + cn]       = make_float2(acc[mi][nj][0], acc[mi][nj][1]);
            *(float2*)&Ds[(rm + 8) * 132 + cn] = make_float2(acc[mi][nj][2], acc[mi][nj][3]);
        }
    __syncthreads();

    if (mode == 2) {
        const int nr = tid >> 1, mc = (tid & 1) * 64;
        const int b = m0 >> 11, tbase = m0 & 2047;
        const float bi = bias[n0 + nr];
        const size_t obase = ((size_t)(b * CCH + n0 + nr)) * TLEN + tbase + mc;
        #pragma unroll 4
        for (int i = 0; i < 64; i += 4) {
            float4 v;
            v.x = Ds[(mc + i + 0) * 132 + nr];
            v.y = Ds[(mc + i + 1) * 132 + nr];
            v.z = Ds[(mc + i + 2) * 132 + nr];
            v.w = Ds[(mc + i + 3) * 132 + nr];
            float4 rr = *(const float4*)(resid + obase + i);
            v.x += bi + rr.x; v.y += bi + rr.y; v.z += bi + rr.z; v.w += bi + rr.w;
            *(float4*)(C + obase + i) = v;
        }
    } else if (mode == 1) {
        if (n0 < HID) {
            const int r = tid >> 1, c = (tid & 1) * 64;
            const int h = (n0 + c) >> 6;
            __half* dst = g_kh + ((size_t)h * LKV + m0 + r) * DD;
            #pragma unroll 4
            for (int j = 0; j < 64; j += 2) {
                float v0 = (Ds[r * 132 + c + j] + bias[n0 + c + j]) * SCALE;
                float v1 = (Ds[r * 132 + c + j + 1] + bias[n0 + c + j + 1]) * SCALE;
                *(__half2*)(dst + j) = __floats2half2_rn(v0, v1);
            }
        } else {
            // V: write transposed g_vt[d][l]
            const int dc = tid >> 1, lh = (tid & 1) * 64;
            const float bi = bias[n0 + dc];
            __half* dst = g_vt + (size_t)(n0 - HID + dc) * LKV + m0 + lh;
            #pragma unroll 4
            for (int j = 0; j < 64; j += 2) {
                float v0 = Ds[(lh + j) * 132 + dc] + bi;
                float v1 = Ds[(lh + j + 1) * 132 + dc] + bi;
                *(__half2*)(dst + j) = __floats2half2_rn(v0, v1);
            }
        }
    } else {
        const int r = tid >> 1, c = (tid & 1) * 64;
        const int b = m0 >> 11, t = (m0 & 2047) + r;
        const int h = (n0 + c) >> 6;
        __half* dst = g_qh + (((size_t)(b * HH + h)) * TLEN + t) * DD;
        #pragma unroll 4
        for (int j = 0; j < 64; j += 2) {
            float v0 = (Ds[r * 132 + c + j] + bias[n0 + c + j]) * SCALE;
            float v1 = (Ds[r * 132 + c + j + 1] + bias[n0 + c + j + 1]) * SCALE;
            *(__half2*)(dst + j) = __floats2half2_rn(v0, v1);
        }
    }
}

// ============================================================
// Flash attention (fp16 mma, online softmax in registers)
// block = (b, h, 128 queries), 8 warps x 16 query rows
// KV chunks of 64 keys, double-buffered cp.async
// ============================================================
#define QSTR 72
#define KSTR 72
#define KCH  (64 * KSTR)              // halfs per K/V stage
#define ATTN_SMEM ((128 * QSTR + 4 * KCH) * 2)   // 55296 bytes

__global__ __launch_bounds__(256, 2) void attn_fa() {
    extern __shared__ __half hsm[];
    __half* Qs = hsm;                 // [128][72]
    __half* Ks = Qs + 128 * QSTR;     // 2 x [64][72]
    __half* Vs = Ks + 2 * KCH;        // 2 x [64][72]  (d-major: row=d, col=l)
    const uint32_t ksb = smem_u32(Ks), vsb = smem_u32(Vs);
    const int tid = threadIdx.x, wid = tid >> 5, lane = tid & 31;
    const int g = lane >> 2, tg = lane & 3;
    const int b = blockIdx.z, h = blockIdx.y, q0 = blockIdx.x * 128;
    const int wm = wid * 16;

    // Q: 128 rows x 128B, cp.async
    {
        const __half* Qg = g_qh + (((size_t)(b * HH + h)) * TLEN + q0) * DD;
        uint32_t qd = smem_u32(Qs);
        #pragma unroll
        for (int j = 0; j < 4; j++) {
            int e = tid + j * 256, r = e >> 3, c = (e & 7) * 8;
            CP_ASYNC(qd + (r * QSTR + c) * 2, Qg + (size_t)r * DD + c);
        }
    }

    const int rk = tid >> 3, ck = (tid & 7) * 8;
    #define APF(i) do { \
        int _buf = (i) & 1; \
        const __half* _ks = g_kh + ((size_t)h * LKV + (i) * 64 + rk) * DD + ck; \
        uint32_t _kd = ksb + _buf * (KCH * 2) + (rk * KSTR + ck) * 2; \
        CP_ASYNC(_kd, _ks); \
        CP_ASYNC(_kd + 32 * KSTR * 2, _ks + (size_t)32 * DD); \
        const __half* _vs = g_vt + (size_t)(h * 64 + rk) * LKV + (i) * 64 + ck; \
        uint32_t _vd = vsb + _buf * (KCH * 2) + (rk * KSTR + ck) * 2; \
        CP_ASYNC(_vd, _vs); \
        CP_ASYNC(_vd + 32 * KSTR * 2, _vs + (size_t)32 * LKV); \
        CP_COMMIT(); \
    } while (0)

    APF(0);
    APF(1);

    float oacc[8][4] = {};
    float m0r = -1e30f, m1r = -1e30f, l0r = 0.f, l1r = 0.f;

    for (int i = 0; i < 8; i++) {
        if (i == 7) CP_WAIT(0); else CP_WAIT(1);
        __syncthreads();
        const __half* ks = Ks + (i & 1) * KCH;
        const __half* vs = Vs + (i & 1) * KCH;

        // ---- S = Q K^T for this 64-key chunk ----
        float sf[8][4] = {};
        #pragma unroll
        for (int kk = 0; kk < 4; kk++) {
            const int k = kk * 16;
            uint32_t a[4];
            a[0] = U32(Qs + (wm + g) * QSTR + k + 2 * tg);
            a[1] = U32(Qs + (wm + g + 8) * QSTR + k + 2 * tg);
            a[2] = U32(Qs + (wm + g) * QSTR + k + 8 + 2 * tg);
            a[3] = U32(Qs + (wm + g + 8) * QSTR + k + 8 + 2 * tg);
            #pragma unroll
            for (int nj = 0; nj < 8; nj++) {
                const int nr = nj * 8 + g;
                uint32_t b0 = U32(ks + nr * KSTR + k + 2 * tg);
                uint32_t b1 = U32(ks + nr * KSTR + k + 8 + 2 * tg);
                mma16(sf[nj], a, b0, b1);
            }
        }

        // ---- online softmax update ----
        float mx0 = m0r, mx1 = m1r;
        #pragma unroll
        for (int nj = 0; nj < 8; nj++) {
            mx0 = fmaxf(mx0, fmaxf(sf[nj][0], sf[nj][1]));
            mx1 = fmaxf(mx1, fmaxf(sf[nj][2], sf[nj][3]));
        }
        mx0 = fmaxf(mx0, __shfl_xor_sync(0xffffffffu, mx0, 1));
        mx0 = fmaxf(mx0, __shfl_xor_sync(0xffffffffu, mx0, 2));
        mx1 = fmaxf(mx1, __shfl_xor_sync(0xffffffffu, mx1, 1));
        mx1 = fmaxf(mx1, __shfl_xor_sync(0xffffffffu, mx1, 2));
        const float f0 = __expf(m0r - mx0), f1 = __expf(m1r - mx1);
        float s0 = 0.f, s1 = 0.f;
        uint32_t ph01[8], ph23[8];
        #pragma unroll
        for (int nj = 0; nj < 8; nj++) {
            float p0 = __expf(sf[nj][0] - mx0), p1 = __expf(sf[nj][1] - mx0);
            float p2 = __expf(sf[nj][2] - mx1), p3 = __expf(sf[nj][3] - mx1);
            s0 += p0 + p1; s1 += p2 + p3;
            ph01[nj] = packh2(p0, p1);
            ph23[nj] = packh2(p2, p3);
        }
        s0 += __shfl_xor_sync(0xffffffffu, s0, 1);
        s0 += __shfl_xor_sync(0xffffffffu, s0, 2);
        s1 += __shfl_xor_sync(0xffffffffu, s1, 1);
        s1 += __shfl_xor_sync(0xffffffffu, s1, 2);
        l0r = l0r * f0 + s0;  l1r = l1r * f1 + s1;
        m0r = mx0;  m1r = mx1;
        #pragma unroll
        for (int nj = 0; nj < 8; nj++) {
            oacc[nj][0] *= f0; oacc[nj][1] *= f0;
            oacc[nj][2] *= f1; oacc[nj][3] *= f1;
        }

        // ---- O += P V (P fragments come straight from S fragments) ----
        #pragma unroll
        for (int kk = 0; kk < 4; kk++) {
            const int k = kk * 16;
            uint32_t a[4] = { ph01[2 * kk], ph23[2 * kk], ph01[2 * kk + 1], ph23[2 * kk + 1] };
            #pragma unroll
            for (int nj = 0; nj < 8; nj++) {
                const int nr = nj * 8 + g;
                uint32_t b0 = U32(vs + nr * KSTR + k + 2 * tg);
                uint32_t b1 = U32(vs + nr * KSTR + k + 8 + 2 * tg);
                mma16(oacc[nj], a, b0, b1);
            }
        }
        __syncthreads();
        if (i + 2 < 8) APF(i + 2);
    }

    // ---- epilogue: normalize, write fp16 to g_ao [m][h*64+d] ----
    const float inv0 = 1.0f / l0r, inv1 = 1.0f / l1r;
    const int q = q0 + wm + g;
    __half* dst0 = g_ao + ((size_t)b * TLEN + q) * HID + h * 64;
    __half* dst1 = dst0 + (size_t)8 * HID;
    #pragma unroll
    for (int nj = 0; nj < 8; nj++) {
        const int d = nj * 8 + 2 * tg;
        *(__half2*)(dst0 + d) = __floats2half2_rn(oacc[nj][0] * inv0, oacc[nj][1] * inv0);
        *(__half2*)(dst1 + d) = __floats2half2_rn(oacc[nj][2] * inv1, oacc[nj][3] * inv1);
    }
}

// ============================================================
extern "C" void kernel_launch(void* const* d_in, const int* in_sizes, int n_in,
                              void* d_out, int out_size) {
    const float* inpt  = (const float*)d_in[0];
    const float* aux   = (const float*)d_in[1];
    const float* q_w   = (const float*)d_in[2];
    const float* q_b   = (const float*)d_in[3];
    const float* kv_w  = (const float*)d_in[4];
    const float* kv_b  = (const float*)d_in[5];
    const float* out_w = (const float*)d_in[6];
    const float* out_b = (const float*)d_in[7];
    float* out = (float*)d_out;

    void *p_qw, *p_kvw, *p_ow, *p_aux, *p_xt, *p_ao;
    cudaGetSymbolAddress(&p_qw, g_qw);
    cudaGetSymbolAddress(&p_kvw, g_kvw);
    cudaGetSymbolAddress(&p_ow, g_ow);
    cudaGetSymbolAddress(&p_aux, g_aux);
    cudaGetSymbolAddress(&p_xt, g_xt);
    cudaGetSymbolAddress(&p_ao, g_ao);

    cudaFuncSetAttribute(gemm_mma, cudaFuncAttributeMaxDynamicSharedMemorySize, GEMM_SMEM);
    cudaFuncSetAttribute(attn_fa, cudaFuncAttributeMaxDynamicSharedMemorySize, ATTN_SMEM);

    round_half<<<(HID * CCH / 4 + 255) / 256, 256>>>((const float4*)q_w, (__half*)p_qw, HID * CCH / 4);
    round_half<<<(2 * HID * CCH / 4 + 255) / 256, 256>>>((const float4*)kv_w, (__half*)p_kvw, 2 * HID * CCH / 4);
    round_half<<<(CCH * HID / 4 + 255) / 256, 256>>>((const float4*)out_w, (__half*)p_ow, CCH * HID / 4);
    round_half<<<(LKV * CCH / 4 + 255) / 256, 256>>>((const float4*)aux, (__half*)p_aux, LKV * CCH / 4);
    transpose_half<<<dim3(TLEN / 32, CCH / 32, BSZ), 256>>>(inpt);

    gemm_mma<<<dim3(16, 4), 256, GEMM_SMEM>>>((const __half*)p_aux, (const __half*)p_kvw,
                                              kv_b, nullptr, nullptr, 1);
    gemm_mma<<<dim3(8, 64), 256, GEMM_SMEM>>>((const __half*)p_xt, (const __half*)p_qw,
                                              q_b, nullptr, nullptr, 0);

    attn_fa<<<dim3(TLEN / 128, HH, BSZ), 256, ATTN_SMEM>>>();

    gemm_mma<<<dim3(8, 64), 256, GEMM_SMEM>>>((const __half*)p_ao, (const __half*)p_ow,
                                              out_b, out, inpt, 2);
}

// round 7
// speedup vs baseline: 8.9295x; 1.2166x over previous
#include <cuda_runtime.h>
#include <cuda_fp16.h>
#include <cstdint>

#define BSZ   4
#define CCH   1024
#define TLEN  2048
#define LKV   512
#define HH    16
#define DD    64
#define HID   1024
#define SCALE 0.35355339059327373f   // (1024/16)^-0.25

// ---------------- scratch (__device__ globals; allocation-free) ----------------
__device__ __half g_xt [BSZ * TLEN * CCH];   // inpt transposed, fp16
__device__ __half g_qw [HID * CCH];
__device__ __half g_kvw[2 * HID * CCH];
__device__ __half g_ow [CCH * HID];
__device__ __half g_aux[LKV * CCH];
__device__ __half g_qh [BSZ * HH * TLEN * DD]; // q head-major [b][h][t][d], *SCALE
__device__ __half g_kh [HH * LKV * DD];        // k head-major [h][l][d], *SCALE
__device__ __half g_vt [HID * LKV];            // v transposed [h*64+d][l]
__device__ __half g_ao [BSZ * TLEN * HID];     // attention out [m][j]

// ---------------- helpers ----------------
__device__ __forceinline__ uint32_t smem_u32(const void* p) {
    uint32_t a;
    asm("{ .reg .u64 t; cvta.to.shared.u64 t, %1; cvt.u32.u64 %0, t; }" : "=r"(a) : "l"(p));
    return a;
}
__device__ __forceinline__ uint32_t packh2(float x, float y) {
    __half2 h = __floats2half2_rn(x, y);
    return *(uint32_t*)&h;
}

#define CP_ASYNC(dst, src) asm volatile("cp.async.cg.shared.global [%0], [%1], 16;" :: "r"(dst), "l"(src) : "memory")
#define CP_COMMIT()        asm volatile("cp.async.commit_group;" ::: "memory")
#define CP_WAIT(n)         asm volatile("cp.async.wait_group %0;" :: "n"(n) : "memory")

__device__ __forceinline__ void mma16(float* d, const uint32_t* a, uint32_t b0, uint32_t b1) {
    asm volatile("mma.sync.aligned.m16n8k16.row.col.f32.f16.f16.f32 "
        "{%0,%1,%2,%3}, {%4,%5,%6,%7}, {%8,%9}, {%0,%1,%2,%3};"
        : "+f"(d[0]), "+f"(d[1]), "+f"(d[2]), "+f"(d[3])
        : "r"(a[0]), "r"(a[1]), "r"(a[2]), "r"(a[3]), "r"(b0), "r"(b1));
}
__device__ __forceinline__ void ldmx4(uint32_t* r, uint32_t addr) {
    asm volatile("ldmatrix.sync.aligned.m8n8.x4.shared.b16 {%0,%1,%2,%3}, [%4];"
        : "=r"(r[0]), "=r"(r[1]), "=r"(r[2]), "=r"(r[3]) : "r"(addr));
}

// ============================================================
// prep: all weight/aux fp32 -> fp16 in one launch
// ============================================================
#define N4_QW  (HID * CCH / 4)
#define N4_KVW (2 * HID * CCH / 4)
#define N4_OW  (CCH * HID / 4)
#define N4_AUX (LKV * CCH / 4)
#define N4_TOT (N4_QW + N4_KVW + N4_OW + N4_AUX)

__global__ __launch_bounds__(256) void round_all(const float4* __restrict__ s_qw,
                                                 const float4* __restrict__ s_kvw,
                                                 const float4* __restrict__ s_ow,
                                                 const float4* __restrict__ s_aux) {
    int i = blockIdx.x * 256 + threadIdx.x;
    const float4* src;
    __half* dst;
    int j;
    if (i < N4_QW) { src = s_qw; dst = g_qw; j = i; }
    else if (i < N4_QW + N4_KVW) { src = s_kvw; dst = g_kvw; j = i - N4_QW; }
    else if (i < N4_QW + N4_KVW + N4_OW) { src = s_ow; dst = g_ow; j = i - N4_QW - N4_KVW; }
    else if (i < N4_TOT) { src = s_aux; dst = g_aux; j = i - N4_QW - N4_KVW - N4_OW; }
    else return;
    float4 v = src[j];
    __half2* d2 = (__half2*)(dst + 4 * (size_t)j);
    d2[0] = __floats2half2_rn(v.x, v.y);
    d2[1] = __floats2half2_rn(v.z, v.w);
}

__global__ __launch_bounds__(256) void transpose_half(const float* __restrict__ in) {
    __shared__ float tile[32][33];
    int b = blockIdx.z, t0 = blockIdx.x * 32, c0 = blockIdx.y * 32;
    int tx = threadIdx.x & 31, ty = threadIdx.x >> 5;
    const float* p = in + ((size_t)b * CCH + c0) * TLEN + t0;
    #pragma unroll
    for (int r = 0; r < 4; r++)
        tile[ty + 8 * r][tx] = p[(size_t)(ty + 8 * r) * TLEN + tx];
    __syncthreads();
    #pragma unroll
    for (int r = 0; r < 4; r++)
        g_xt[((size_t)b * TLEN + t0 + ty + 8 * r) * CCH + c0 + tx] =
            __float2half_rn(tile[tx][ty + 8 * r]);
}

// ============================================================
// fp16 mma GEMM: 128x128 tile, K=1024, BK=64, ldmatrix fragments
// mode 0: g_qh[b][h][t][d] = h((acc+bias)*SCALE)     (q proj)
// mode 1: n<1024 -> g_kh ; else g_vt (transposed)    (kv proj)
// mode 2: out[b][n][t] = acc + bias[n] + resid       (out proj + residual)
// ============================================================
#define AH 72                          // smem stride in halfs (64 + 8 pad)
#define STAGE_H (128 * AH)             // halfs per stage per matrix
#define GEMM_SMEM (2 * 2 * STAGE_H * 2)   // 73728 bytes; epilogue Ds (67584) fits

__global__ __launch_bounds__(256) void gemm_mma(const __half* __restrict__ A,
                                                const __half* __restrict__ W,
                                                const float* __restrict__ bias,
                                                float* __restrict__ C,
                                                const float* __restrict__ resid,
                                                int mode) {
    extern __shared__ float sm[];
    __half* As = (__half*)sm;                    // [2][128][72]
    __half* Bs = As + 2 * STAGE_H;
    const uint32_t asb = smem_u32(As), bsb = smem_u32(Bs);
    const int tid = threadIdx.x, lane = tid & 31, warp = tid >> 5;
    const int g = lane >> 2, tg = lane & 3;
    const int m_w = (warp & 3) * 32, n_w = (warp >> 2) * 64;
    const int m0 = blockIdx.y * 128, n0 = blockIdx.x * 128;

    const int r0 = tid >> 3, c0 = (tid & 7) * 8;
    const __half* gA = A + (size_t)(m0 + r0) * 1024 + c0;
    const __half* gW = W + (size_t)(n0 + r0) * 1024 + c0;
    const uint32_t dA = asb + (r0 * AH + c0) * 2;
    const uint32_t dB = bsb + (r0 * AH + c0) * 2;

    // ldmatrix per-lane byte offsets
    const uint32_t a_off = ((lane & 15) * AH + ((lane >> 4) << 3)) * 2;
    const uint32_t b_off = ((((lane >> 4) << 3) + (lane & 7)) * AH + (((lane >> 3) & 1) << 3)) * 2;

    float acc[2][8][4] = {};

    #define LOAD_STAGE(s, k0) do { \
        uint32_t off = (uint32_t)(s) * (STAGE_H * 2); \
        _Pragma("unroll") \
        for (int j = 0; j < 4; j++) { \
            CP_ASYNC(dA + off + j * 32 * AH * 2, gA + (k0) + (size_t)j * 32 * 1024); \
            CP_ASYNC(dB + off + j * 32 * AH * 2, gW + (k0) + (size_t)j * 32 * 1024); \
        } \
        CP_COMMIT(); \
    } while (0)

    LOAD_STAGE(0, 0);
    LOAD_STAGE(1, 64);

    for (int kt = 0; kt < 16; kt++) {
        const int s = kt & 1;
        if (kt >= 14) CP_WAIT(0); else CP_WAIT(1);
        __syncthreads();
        const uint32_t abase = asb + s * (STAGE_H * 2) + m_w * AH * 2 + a_off;
        const uint32_t bbase = bsb + s * (STAGE_H * 2) + n_w * AH * 2 + b_off;
        #pragma unroll
        for (int ks = 0; ks < 4; ks++) {
            uint32_t a0[4], a1[4], bb[4][4];
            ldmx4(a0, abase + ks * 32);
            ldmx4(a1, abase + 16 * AH * 2 + ks * 32);
            #pragma unroll
            for (int t = 0; t < 4; t++)
                ldmx4(bb[t], bbase + t * 16 * AH * 2 + ks * 32);
            #pragma unroll
            for (int nj = 0; nj < 8; nj++) {
                uint32_t b0 = bb[nj >> 1][(nj & 1) * 2];
                uint32_t b1 = bb[nj >> 1][(nj & 1) * 2 + 1];
                mma16(acc[0][nj], a0, b0, b1);
                mma16(acc[1][nj], a1, b0, b1);
            }
        }
        __syncthreads();
        if (kt + 2 < 16) LOAD_STAGE(s, (kt + 2) * 64);
    }
    #undef LOAD_STAGE

    // ---- epilogue via smem Ds[128][132] (fp32) ----
    float* Ds = sm;
    __syncthreads();
    #pragma unroll
    for (int mi = 0; mi < 2; mi++)
        #pragma unroll
        for (int nj = 0; nj < 8; nj++) {
            const int rm = m_w + mi * 16 + g;
            const int cn = n_w + nj * 8 + 2 * tg;
            *(float2*)&Ds[rm * 132 + cn]       = make_float2(acc[mi][nj][0], acc[mi][nj][1]);
            *(float2*)&Ds[(rm + 8) * 132 + cn] = make_float2(acc[mi][nj][2], acc[mi][nj][3]);
        }
    __syncthreads();

    if (mode == 2) {
        const int nr = tid >> 1, mc = (tid & 1) * 64;
        const int b = m0 >> 11, tbase = m0 & 2047;
        const float bi = bias[n0 + nr];
        const size_t obase = ((size_t)(b * CCH + n0 + nr)) * TLEN + tbase + mc;
        #pragma unroll 4
        for (int i = 0; i < 64; i += 4) {
            float4 v;
            v.x = Ds[(mc + i + 0) * 132 + nr];
            v.y = Ds[(mc + i + 1) * 132 + nr];
            v.z = Ds[(mc + i + 2) * 132 + nr];
            v.w = Ds[(mc + i + 3) * 132 + nr];
            float4 rr = *(const float4*)(resid + obase + i);
            v.x += bi + rr.x; v.y += bi + rr.y; v.z += bi + rr.z; v.w += bi + rr.w;
            *(float4*)(C + obase + i) = v;
        }
    } else if (mode == 1) {
        if (n0 < HID) {
            const int r = tid >> 1, c = (tid & 1) * 64;
            const int h = (n0 + c) >> 6;
            __half* dst = g_kh + ((size_t)h * LKV + m0 + r) * DD;
            #pragma unroll 4
            for (int j = 0; j < 64; j += 2) {
                float v0 = (Ds[r * 132 + c + j] + bias[n0 + c + j]) * SCALE;
                float v1 = (Ds[r * 132 + c + j + 1] + bias[n0 + c + j + 1]) * SCALE;
                *(__half2*)(dst + j) = __floats2half2_rn(v0, v1);
            }
        } else {
            // V: write transposed g_vt[d][l]
            const int dc = tid >> 1, lh = (tid & 1) * 64;
            const float bi = bias[n0 + dc];
            __half* dst = g_vt + (size_t)(n0 - HID + dc) * LKV + m0 + lh;
            #pragma unroll 4
            for (int j = 0; j < 64; j += 2) {
                float v0 = Ds[(lh + j) * 132 + dc] + bi;
                float v1 = Ds[(lh + j + 1) * 132 + dc] + bi;
                *(__half2*)(dst + j) = __floats2half2_rn(v0, v1);
            }
        }
    } else {
        const int r = tid >> 1, c = (tid & 1) * 64;
        const int b = m0 >> 11, t = (m0 & 2047) + r;
        const int h = (n0 + c) >> 6;
        __half* dst = g_qh + (((size_t)(b * HH + h)) * TLEN + t) * DD;
        #pragma unroll 4
        for (int j = 0; j < 64; j += 2) {
            float v0 = (Ds[r * 132 + c + j] + bias[n0 + c + j]) * SCALE;
            float v1 = (Ds[r * 132 + c + j + 1] + bias[n0 + c + j + 1]) * SCALE;
            *(__half2*)(dst + j) = __floats2half2_rn(v0, v1);
        }
    }
}

// ============================================================
// Flash attention (fp16 mma + ldmatrix, online softmax in regs)
// block = (b, h, 128 queries), 8 warps x 16 query rows
// KV chunks of 64 keys, double-buffered cp.async; Q frags hoisted
// ============================================================
#define QSTR 72
#define KSTR 72
#define KCH  (64 * KSTR)              // halfs per K/V stage
#define ATTN_SMEM ((128 * QSTR + 4 * KCH) * 2)   // 55296 bytes

__global__ __launch_bounds__(256, 2) void attn_fa() {
    extern __shared__ __half hsm[];
    __half* Qs = hsm;                 // [128][72]
    __half* Ks = Qs + 128 * QSTR;     // 2 x [64][72]   row=key, col=d
    __half* Vs = Ks + 2 * KCH;        // 2 x [64][72]   row=d, col=key
    const uint32_t qsb = smem_u32(Qs), ksb = smem_u32(Ks), vsb = smem_u32(Vs);
    const int tid = threadIdx.x, wid = tid >> 5, lane = tid & 31;
    const int b = blockIdx.z, h = blockIdx.y, q0 = blockIdx.x * 128;
    const int wm = wid * 16;

    const uint32_t a_off = ((lane & 15) * QSTR + ((lane >> 4) << 3)) * 2;
    const uint32_t b_off = ((((lane >> 4) << 3) + (lane & 7)) * KSTR + (((lane >> 3) & 1) << 3)) * 2;

    // Q: 128 rows x 128B, cp.async (group 0)
    {
        const __half* Qg = g_qh + (((size_t)(b * HH + h)) * TLEN + q0) * DD;
        #pragma unroll
        for (int j = 0; j < 4; j++) {
            int e = tid + j * 256, r = e >> 3, c = (e & 7) * 8;
            CP_ASYNC(qsb + (r * QSTR + c) * 2, Qg + (size_t)r * DD + c);
        }
        CP_COMMIT();
    }

    const int rk = tid >> 3, ck = (tid & 7) * 8;
    #define APF(i) do { \
        int _buf = (i) & 1; \
        const __half* _ks = g_kh + ((size_t)h * LKV + (i) * 64 + rk) * DD + ck; \
        uint32_t _kd = ksb + _buf * (KCH * 2) + (rk * KSTR + ck) * 2; \
        CP_ASYNC(_kd, _ks); \
        CP_ASYNC(_kd + 32 * KSTR * 2, _ks + (size_t)32 * DD); \
        const __half* _vs = g_vt + (size_t)(h * 64 + rk) * LKV + (i) * 64 + ck; \
        uint32_t _vd = vsb + _buf * (KCH * 2) + (rk * KSTR + ck) * 2; \
        CP_ASYNC(_vd, _vs); \
        CP_ASYNC(_vd + 32 * KSTR * 2, _vs + (size_t)32 * LKV); \
        CP_COMMIT(); \
    } while (0)

    APF(0);
    APF(1);

    // hoist Q fragments (loop-invariant): wait for Q group only
    uint32_t qfrag[4][4];
    CP_WAIT(2);
    __syncthreads();
    {
        const uint32_t qbase = qsb + wm * QSTR * 2 + a_off;
        #pragma unroll
        for (int ks = 0; ks < 4; ks++) ldmx4(qfrag[ks], qbase + ks * 32);
    }

    float oacc[8][4] = {};
    float m0r = -1e30f, m1r = -1e30f, l0r = 0.f, l1r = 0.f;

    for (int i = 0; i < 8; i++) {
        if (i == 7) CP_WAIT(0); else CP_WAIT(1);
        __syncthreads();
        const uint32_t kbase = ksb + (i & 1) * (KCH * 2) + b_off;
        const uint32_t vbase = vsb + (i & 1) * (KCH * 2) + b_off;

        // ---- S = Q K^T for this 64-key chunk ----
        float sf[8][4] = {};
        #pragma unroll
        for (int ks = 0; ks < 4; ks++) {
            uint32_t bb[4][4];
            #pragma unroll
            for (int t = 0; t < 4; t++)
                ldmx4(bb[t], kbase + t * 16 * KSTR * 2 + ks * 32);
            #pragma unroll
            for (int nj = 0; nj < 8; nj++)
                mma16(sf[nj], qfrag[ks], bb[nj >> 1][(nj & 1) * 2], bb[nj >> 1][(nj & 1) * 2 + 1]);
        }

        // ---- online softmax update ----
        float mx0 = m0r, mx1 = m1r;
        #pragma unroll
        for (int nj = 0; nj < 8; nj++) {
            mx0 = fmaxf(mx0, fmaxf(sf[nj][0], sf[nj][1]));
            mx1 = fmaxf(mx1, fmaxf(sf[nj][2], sf[nj][3]));
        }
        mx0 = fmaxf(mx0, __shfl_xor_sync(0xffffffffu, mx0, 1));
        mx0 = fmaxf(mx0, __shfl_xor_sync(0xffffffffu, mx0, 2));
        mx1 = fmaxf(mx1, __shfl_xor_sync(0xffffffffu, mx1, 1));
        mx1 = fmaxf(mx1, __shfl_xor_sync(0xffffffffu, mx1, 2));
        const float f0 = __expf(m0r - mx0), f1 = __expf(m1r - mx1);
        float s0 = 0.f, s1 = 0.f;
        uint32_t ph01[8], ph23[8];
        #pragma unroll
        for (int nj = 0; nj < 8; nj++) {
            float p0 = __expf(sf[nj][0] - mx0), p1 = __expf(sf[nj][1] - mx0);
            float p2 = __expf(sf[nj][2] - mx1), p3 = __expf(sf[nj][3] - mx1);
            s0 += p0 + p1; s1 += p2 + p3;
            ph01[nj] = packh2(p0, p1);
            ph23[nj] = packh2(p2, p3);
        }
        s0 += __shfl_xor_sync(0xffffffffu, s0, 1);
        s0 += __shfl_xor_sync(0xffffffffu, s0, 2);
        s1 += __shfl_xor_sync(0xffffffffu, s1, 1);
        s1 += __shfl_xor_sync(0xffffffffu, s1, 2);
        l0r = l0r * f0 + s0;  l1r = l1r * f1 + s1;
        m0r = mx0;  m1r = mx1;
        #pragma unroll
        for (int nj = 0; nj < 8; nj++) {
            oacc[nj][0] *= f0; oacc[nj][1] *= f0;
            oacc[nj][2] *= f1; oacc[nj][3] *= f1;
        }

        // ---- O += P V (P fragments straight from S fragments) ----
        #pragma unroll
        for (int kk = 0; kk < 4; kk++) {
            uint32_t a[4] = { ph01[2 * kk], ph23[2 * kk], ph01[2 * kk + 1], ph23[2 * kk + 1] };
            uint32_t bb[4][4];
            #pragma unroll
            for (int t = 0; t < 4; t++)
                ldmx4(bb[t], vbase + t * 16 * KSTR * 2 + kk * 32);
            #pragma unroll
            for (int nj = 0; nj < 8; nj++)
                mma16(oacc[nj], a, bb[nj >> 1][(nj & 1) * 2], bb[nj >> 1][(nj & 1) * 2 + 1]);
        }
        __syncthreads();
        if (i + 2 < 8) APF(i + 2);
    }
    #undef APF

    // ---- epilogue: normalize, write fp16 to g_ao [m][h*64+d] ----
    const int g = lane >> 2, tg = lane & 3;
    const float inv0 = 1.0f / l0r, inv1 = 1.0f / l1r;
    const int q = q0 + wm + g;
    __half* dst0 = g_ao + ((size_t)b * TLEN + q) * HID + h * 64;
    __half* dst1 = dst0 + (size_t)8 * HID;
    #pragma unroll
    for (int nj = 0; nj < 8; nj++) {
        const int d = nj * 8 + 2 * tg;
        *(__half2*)(dst0 + d) = __floats2half2_rn(oacc[nj][0] * inv0, oacc[nj][1] * inv0);
        *(__half2*)(dst1 + d) = __floats2half2_rn(oacc[nj][2] * inv1, oacc[nj][3] * inv1);
    }
}

// ============================================================
extern "C" void kernel_launch(void* const* d_in, const int* in_sizes, int n_in,
                              void* d_out, int out_size) {
    const float* inpt  = (const float*)d_in[0];
    const float* aux   = (const float*)d_in[1];
    const float* q_w   = (const float*)d_in[2];
    const float* q_b   = (const float*)d_in[3];
    const float* kv_w  = (const float*)d_in[4];
    const float* kv_b  = (const float*)d_in[5];
    const float* out_w = (const float*)d_in[6];
    const float* out_b = (const float*)d_in[7];
    float* out = (float*)d_out;

    void *p_qw, *p_kvw, *p_ow, *p_aux, *p_xt, *p_ao;
    cudaGetSymbolAddress(&p_qw, g_qw);
    cudaGetSymbolAddress(&p_kvw, g_kvw);
    cudaGetSymbolAddress(&p_ow, g_ow);
    cudaGetSymbolAddress(&p_aux, g_aux);
    cudaGetSymbolAddress(&p_xt, g_xt);
    cudaGetSymbolAddress(&p_ao, g_ao);

    cudaFuncSetAttribute(gemm_mma, cudaFuncAttributeMaxDynamicSharedMemorySize, GEMM_SMEM);
    cudaFuncSetAttribute(attn_fa, cudaFuncAttributeMaxDynamicSharedMemorySize, ATTN_SMEM);

    round_all<<<(N4_TOT + 255) / 256, 256>>>((const float4*)q_w, (const float4*)kv_w,
                                             (const float4*)out_w, (const float4*)aux);
    transpose_half<<<dim3(TLEN / 32, CCH / 32, BSZ), 256>>>(inpt);

    gemm_mma<<<dim3(16, 4), 256, GEMM_SMEM>>>((const __half*)p_aux, (const __half*)p_kvw,
                                              kv_b, nullptr, nullptr, 1);
    gemm_mma<<<dim3(8, 64), 256, GEMM_SMEM>>>((const __half*)p_xt, (const __half*)p_qw,
                                              q_b, nullptr, nullptr, 0);

    attn_fa<<<dim3(TLEN / 128, HH, BSZ), 256, ATTN_SMEM>>>();

    gemm_mma<<<dim3(8, 64), 256, GEMM_SMEM>>>((const __half*)p_ao, (const __half*)p_ow,
                                              out_b, out, inpt, 2);
}